// round 12
// baseline (speedup 1.0000x reference)
#include <cuda_runtime.h>
#include <cstdint>

#define N_NODES 8192
#define DIM 64
#define N_EDGES 16384
#define NEGV -1e10f
#define TINYF 1.17549435e-38f
#define NCY 11       // grid.y strides in k_argmax -> 64*11=704 blocks ~= 1 wave @ 5 blocks/SM
#define QBATCH 16    // candidates per chunk (NCY*QBATCH=176 covers typical C in one chunk)

// ============================================================
// threefry2x32 (verified vs Random123 KAT)
// ============================================================
struct U2 { uint32_t a, b; };

__host__ __device__ constexpr uint32_t rotl32(uint32_t v, int r) {
    return (v << r) | (v >> (32 - r));
}

__host__ __device__ constexpr U2 tf2x32(uint32_t k0, uint32_t k1, uint32_t c0, uint32_t c1) {
    uint32_t ks0 = k0, ks1 = k1, ks2 = k0 ^ k1 ^ 0x1BD11BDAu;
    uint32_t x0 = c0 + ks0, x1 = c1 + ks1;
    x0 += x1; x1 = rotl32(x1, 13); x1 ^= x0;
    x0 += x1; x1 = rotl32(x1, 15); x1 ^= x0;
    x0 += x1; x1 = rotl32(x1, 26); x1 ^= x0;
    x0 += x1; x1 = rotl32(x1, 6);  x1 ^= x0;
    x0 += ks1; x1 += ks2 + 1u;
    x0 += x1; x1 = rotl32(x1, 17); x1 ^= x0;
    x0 += x1; x1 = rotl32(x1, 29); x1 ^= x0;
    x0 += x1; x1 = rotl32(x1, 16); x1 ^= x0;
    x0 += x1; x1 = rotl32(x1, 24); x1 ^= x0;
    x0 += ks2; x1 += ks0 + 2u;
    x0 += x1; x1 = rotl32(x1, 13); x1 ^= x0;
    x0 += x1; x1 = rotl32(x1, 15); x1 ^= x0;
    x0 += x1; x1 = rotl32(x1, 26); x1 ^= x0;
    x0 += x1; x1 = rotl32(x1, 6);  x1 ^= x0;
    x0 += ks0; x1 += ks1 + 3u;
    x0 += x1; x1 = rotl32(x1, 17); x1 ^= x0;
    x0 += x1; x1 = rotl32(x1, 29); x1 ^= x0;
    x0 += x1; x1 = rotl32(x1, 16); x1 ^= x0;
    x0 += x1; x1 = rotl32(x1, 24); x1 ^= x0;
    x0 += ks1; x1 += ks2 + 4u;
    x0 += x1; x1 = rotl32(x1, 13); x1 ^= x0;
    x0 += x1; x1 = rotl32(x1, 15); x1 ^= x0;
    x0 += x1; x1 = rotl32(x1, 26); x1 ^= x0;
    x0 += x1; x1 = rotl32(x1, 6);  x1 ^= x0;
    x0 += ks2; x1 += ks0 + 5u;
    return U2{x0, x1};
}

// Partitionable threefry (modern JAX default)
constexpr uint32_t KP0 = tf2x32(0u, 42u, 0u, 0u).a;
constexpr uint32_t KP1 = tf2x32(0u, 42u, 0u, 0u).b;
constexpr uint32_t KE0 = tf2x32(0u, 42u, 0u, 1u).a;
constexpr uint32_t KE1 = tf2x32(0u, 42u, 0u, 1u).b;
constexpr uint32_t KS0 = tf2x32(0u, 42u, 0u, 2u).a;
constexpr uint32_t KS1 = tf2x32(0u, 42u, 0u, 2u).b;

__device__ __forceinline__ uint32_t pbits32(uint32_t k0, uint32_t k1, uint32_t idx) {
    U2 r = tf2x32(k0, k1, 0u, idx);
    return r.a ^ r.b;
}

__device__ __forceinline__ unsigned long long pbits64(uint32_t k0, uint32_t k1, uint32_t idx) {
    U2 r = tf2x32(k0, k1, 0u, idx);
    return ((unsigned long long)r.a << 32) | (unsigned long long)r.b;
}

__device__ __forceinline__ float u01f(uint32_t bits) {
    return __uint_as_float((bits >> 9) | 0x3f800000u) - 1.0f;
}

__device__ __forceinline__ double u01d(unsigned long long bits) {
    return __longlong_as_double((long long)((bits >> 12) | 0x3FF0000000000000ull)) - 1.0;
}

// f64 erfinv: Giles-poly init + Newton refinement with libm erf/erfc
__device__ double erfinv64(double u) {
    double au = fabs(u);
    double w = -log1p(-au * au);
    double x;
    const double C = 0.8862269254527580;  // sqrt(pi)/2
    if (w < 5.0) {
        double ww = w - 2.5;
        double p = 2.81022636e-08;
        p = fma(p, ww, 3.43273939e-07);
        p = fma(p, ww, -3.5233877e-06);
        p = fma(p, ww, -4.39150654e-06);
        p = fma(p, ww, 0.00021858087);
        p = fma(p, ww, -0.00125372503);
        p = fma(p, ww, -0.00417768164);
        p = fma(p, ww, 0.246640727);
        p = fma(p, ww, 1.50140941);
        x = p * au;
#pragma unroll
        for (int it = 0; it < 3; ++it)
            x += (au - erf(x)) * C * exp(x * x);
    } else {
        double eps = 1.0 - au;  // exact (au in [0.9966, 1))
        if (w < 16.0) {
            double ww = sqrt(w) - 3.0;
            double p = -0.000200214257;
            p = fma(p, ww, 0.000100950558);
            p = fma(p, ww, 0.00134934322);
            p = fma(p, ww, -0.00367342844);
            p = fma(p, ww, 0.00573950773);
            p = fma(p, ww, -0.0076224613);
            p = fma(p, ww, 0.00943887047);
            p = fma(p, ww, 1.00167406);
            p = fma(p, ww, 2.83297682);
            x = p * au;
        } else {
            double t = -log(eps);
            x = sqrt(t - 0.5 * log(t) - 0.5723649429247001);
        }
#pragma unroll
        for (int it = 0; it < 5; ++it)
            x += (erfc(x) - eps) * C * exp(x * x);
    }
    return copysign(x, u);
}

// ============================================================
// Scratch (static device globals)
// ============================================================
__device__ float g_queries[N_NODES * DIM];
__device__ float g_qn[N_NODES];
__device__ float g_hn[N_NODES];
__device__ unsigned char g_gens[N_NODES];
__device__ int g_genlist[N_NODES];
__device__ int g_cand_of[N_NODES];
__device__ unsigned char g_drop[N_NODES];
__device__ int g_gencount;
__device__ unsigned long long g_best[N_NODES];
__device__ float g_cs[N_EDGES];
__device__ int g_eactive;
__device__ int g_fi[N_NODES];
__device__ int g_fj[N_NODES];
__device__ int g_nall;
__device__ int g_nclip;

// ============================================================
// K1: queries/qn/hn/gens. 256 blocks x 256 threads; warp = 4 nodes.
// ============================================================
__global__ void k_prep(const float* __restrict__ nodes, const float* __restrict__ Wq,
                       const float* __restrict__ bq, const float* __restrict__ Wp,
                       const float* __restrict__ bp, const float* __restrict__ an) {
    __shared__ float Wqs[64 * 64];
    __shared__ float bqs[64];
    int tid = threadIdx.x;
    for (int k = tid; k < 4096; k += 256) Wqs[k] = Wq[k];
    if (tid < 64) bqs[tid] = bq[tid];
    __syncthreads();

    int warp = tid >> 5, lane = tid & 31;
    float wp0 = Wp[lane], wp1 = Wp[32 + lane];
    float bp0 = bp[0];

    for (int n = 0; n < 4; ++n) {
        int i = blockIdx.x * 32 + warp * 4 + n;

        float nv0 = nodes[i * 64 + lane];
        float nv1 = nodes[i * 64 + 32 + lane];

        float h = nv0 * nv0 + nv1 * nv1;
        float pdot = nv0 * wp0 + nv1 * wp1;
        for (int o = 16; o; o >>= 1) {
            h += __shfl_xor_sync(0xFFFFFFFFu, h, o);
            pdot += __shfl_xor_sync(0xFFFFFFFFu, pdot, o);
        }

        float acc0 = bqs[lane], acc1 = bqs[32 + lane];
#pragma unroll
        for (int d = 0; d < 32; ++d) {
            float nv = __shfl_sync(0xFFFFFFFFu, nv0, d);
            acc0 = fmaf(nv, Wqs[d * 64 + lane], acc0);
            acc1 = fmaf(nv, Wqs[d * 64 + 32 + lane], acc1);
        }
#pragma unroll
        for (int d = 0; d < 32; ++d) {
            float nv = __shfl_sync(0xFFFFFFFFu, nv1, d);
            acc0 = fmaf(nv, Wqs[(32 + d) * 64 + lane], acc0);
            acc1 = fmaf(nv, Wqs[(32 + d) * 64 + 32 + lane], acc1);
        }
        g_queries[i * 64 + lane] = acc0;
        g_queries[i * 64 + 32 + lane] = acc1;

        float q2 = acc0 * acc0 + acc1 * acc1;
        for (int o = 16; o; o >>= 1) q2 += __shfl_xor_sync(0xFFFFFFFFu, q2, o);

        if (lane == 0) {
            g_hn[i] = h;
            g_qn[i] = q2;
            float x = pdot + bp0;
            float prob = 1.0f / (1.0f + expf(-x));
            double u = u01d(pbits64(KP0, KP1, (uint32_t)i));
            g_gens[i] = (u < (double)(prob * an[i])) ? 1 : 0;
        }
    }
}

// ============================================================
// K2: fused ae-cumsum + gens-compaction via shfl warp scans.
// 1 block x 1024 threads; 4 barriers total.
// (0/1 float sums <= 16384 are exact under any association)
// ============================================================
__global__ void k_scancompact(const float* __restrict__ ae) {
    __shared__ float wsf[32];
    __shared__ int wsi[32];
    int t = threadIdx.x, w = t >> 5, l = t & 31;

    // ---- Part A: inclusive cumsum of active_edges (16/thread) ----
    float loc[16];
    float s = 0.f;
#pragma unroll
    for (int k = 0; k < 16; ++k) { loc[k] = ae[t * 16 + k]; s += loc[k]; }
    float sc = s;
#pragma unroll
    for (int o = 1; o < 32; o <<= 1) {
        float v = __shfl_up_sync(0xFFFFFFFFu, sc, o);
        if (l >= o) sc += v;
    }
    if (l == 31) wsf[w] = sc;
    __syncthreads();
    if (w == 0) {
        float ws = wsf[l];
#pragma unroll
        for (int o = 1; o < 32; o <<= 1) {
            float v = __shfl_up_sync(0xFFFFFFFFu, ws, o);
            if (l >= o) ws += v;
        }
        wsf[l] = ws;
    }
    __syncthreads();
    float run = (w > 0 ? wsf[w - 1] : 0.f) + (sc - s);
#pragma unroll
    for (int k = 0; k < 16; ++k) { run += loc[k]; g_cs[t * 16 + k] = run; }
    if (t == 1023) g_eactive = (int)wsf[31];

    // ---- Part B: compact gens (8/thread), cand_of, zero best/drop ----
    unsigned char lg[8];
    int si = 0;
#pragma unroll
    for (int k = 0; k < 8; ++k) { lg[k] = g_gens[t * 8 + k]; si += lg[k]; }
    int sci = si;
#pragma unroll
    for (int o = 1; o < 32; o <<= 1) {
        int v = __shfl_up_sync(0xFFFFFFFFu, sci, o);
        if (l >= o) sci += v;
    }
    if (l == 31) wsi[w] = sci;
    __syncthreads();
    if (w == 0) {
        int ws = wsi[l];
#pragma unroll
        for (int o = 1; o < 32; o <<= 1) {
            int v = __shfl_up_sync(0xFFFFFFFFu, ws, o);
            if (l >= o) ws += v;
        }
        wsi[l] = ws;
    }
    __syncthreads();
    int base = (w > 0 ? wsi[w - 1] : 0) + (sci - si);
#pragma unroll
    for (int k = 0; k < 8; ++k) {
        int idx = t * 8 + k;
        if (lg[k]) { g_genlist[base] = idx; g_cand_of[idx] = base; base++; }
        else g_cand_of[idx] = -1;
    }
    if (t == 1023) g_gencount = wsi[31];
    for (int k = t; k < N_NODES; k += 1024) { g_best[k] = 0ull; g_drop[k] = 0; }
}

// ============================================================
// K3: per-candidate argmax_j(score + gumbel_f32)
// Node row held in registers (16 float4); qs read as float4 BROADCAST
// from smem -> no LDS bottleneck. Sequential FMA order preserved
// (bit-identical scores vs passing kernel).
// ============================================================
__global__ void __launch_bounds__(128, 5)
k_argmax(const float* __restrict__ nodes, const float* __restrict__ an) {
    __shared__ float4 qs4[QBATCH * 16];
    __shared__ float qn_s[QBATCH];
    __shared__ int ii_s[QBATCH];
    __shared__ unsigned long long sbest[QBATCH];
    int t = threadIdx.x;
    int j = blockIdx.x * 128 + t;

    float4 row[16];
    const float4* nr = (const float4*)(nodes + (size_t)j * 64);
#pragma unroll
    for (int d4 = 0; d4 < 16; ++d4) row[d4] = nr[d4];
    float hnj = g_hn[j];
    float anj = an[j];

    int C = g_gencount;
    for (int cbase = blockIdx.y; cbase < C; cbase += NCY * QBATCH) {
        for (int q = t; q < QBATCH * 16; q += 128) {
            int k = q >> 4, d4 = q & 15;
            int c = cbase + k * NCY;
            if (c < C) {
                int i = g_genlist[c];
                qs4[q] = ((const float4*)(g_queries + (size_t)i * 64))[d4];
                if (d4 == 0) { qn_s[k] = g_qn[i]; ii_s[k] = i; }
            }
        }
        if (t < QBATCH) sbest[t] = 0ull;
        __syncthreads();
#pragma unroll 1
        for (int k = 0; k < QBATCH; ++k) {
            int c = cbase + k * NCY;
            if (c >= C) break;
            int i = ii_s[k];
            float num = 0.f;
#pragma unroll
            for (int d4 = 0; d4 < 16; ++d4) {
                float4 q = qs4[k * 16 + d4];   // warp-broadcast LDS.128
                num = fmaf(q.x, row[d4].x, num);
                num = fmaf(q.y, row[d4].y, num);
                num = fmaf(q.z, row[d4].z, num);
                num = fmaf(q.w, row[d4].w, num);
            }
            float s = num / (sqrtf(qn_s[k] * hnj) + 1e-8f);
            s = fminf(fmaxf(s, -10000.f), 10000.f);
            if (!(anj > 0.f)) s = NEGV;
            if (j == i) s = NEGV;
            uint32_t idx = (uint32_t)i * (uint32_t)N_NODES + (uint32_t)j;
            float f = u01f(pbits32(KS0, KS1, idx));
            float u = fmaxf(TINYF, f + TINYF);
            float g = -logf(-logf(u));
            float v = s + g;
            uint32_t ord = __float_as_uint(v);
            ord = (ord & 0x80000000u) ? ~ord : (ord | 0x80000000u);
            unsigned long long enc =
                ((unsigned long long)ord << 32) | (unsigned long long)(~(uint32_t)j);
#pragma unroll
            for (int o = 16; o; o >>= 1) {
                unsigned long long other = __shfl_xor_sync(0xFFFFFFFFu, enc, o);
                if (other > enc) enc = other;
            }
            if ((t & 31) == 0) atomicMax(&sbest[k], enc);
        }
        __syncthreads();
        if (t < QBATCH) {
            int c = cbase + t * NCY;
            if (c < C && sbest[t]) atomicMax(&g_best[c], sbest[t]);
        }
        __syncthreads();
    }
}

// ============================================================
// K4: fused exist-check (one O(E) pass) + ordered compaction + clip.
// 1 block x 256 threads; __syncthreads orders the phases.
// ============================================================
__global__ void k_existfinal(const int* __restrict__ senders, const int* __restrict__ receivers) {
    __shared__ int warpcnt[8];
    __shared__ int warpoff[8];
    __shared__ int running;
    int t = threadIdx.x;
    int C = g_gencount;

    // phase 1: mark drops
    for (int e = t; e < N_EDGES; e += 256) {
        int i = senders[e];
        int c = g_cand_of[i];
        if (c >= 0) {
            int sel = (int)(~(uint32_t)(g_best[c] & 0xFFFFFFFFull));
            if (receivers[e] == sel) g_drop[c] = 1;
        }
    }
    if (t == 0) running = 0;
    __syncthreads();

    // phase 2: ordered compaction
    for (int cbase = 0; cbase < C; cbase += 256) {
        int c = cbase + t;
        bool keep = (c < C) && !g_drop[c];
        unsigned mask = __ballot_sync(0xFFFFFFFFu, keep);
        int w = t >> 5, l = t & 31;
        if (l == 0) warpcnt[w] = __popc(mask);
        __syncthreads();
        if (t == 0) {
            int s = running;
#pragma unroll
            for (int k = 0; k < 8; ++k) { warpoff[k] = s; s += warpcnt[k]; }
            running = s;
        }
        __syncthreads();
        if (keep) {
            int pos = warpoff[w] + __popc(mask & ((1u << l) - 1u));
            g_fi[pos] = g_genlist[c];
            g_fj[pos] = (int)(~(uint32_t)(g_best[c] & 0xFFFFFFFFull));
        }
        __syncthreads();
    }
    if (t == 0) {
        int n = running;
        int ea = g_eactive;
        int allowed = N_EDGES - ea - 1;
        if (allowed < 0) allowed = 0;
        g_nall = n;
        g_nclip = (n < allowed) ? n : allowed;
    }
}

// windowed-any from cumsum: naedges[j]
__device__ __forceinline__ float na_of(int j, int n) {
    float c = g_cs[j];
    int pidx = j - n - 1;
    float prev = (pidx >= 0) ? g_cs[pidx] : 0.f;
    float na = ((c - prev) > 0.f) ? 1.f : 0.f;
    if (j == N_EDGES - 1) na = 0.f;
    return na;
}

// ============================================================
// K5: fused tail + new_edges, float4 I/O (262144 float4 threads)
// ============================================================
__global__ void k_edgetail(const float4* __restrict__ edges4, const float* __restrict__ ae,
                           const int* __restrict__ senders, const int* __restrict__ receivers,
                           float* __restrict__ out) {
    int q = blockIdx.x * blockDim.x + threadIdx.x;   // 0 .. N_EDGES*16-1
    int n = g_nclip;

    if (q < N_EDGES) {
        int jt = q;
        int ea = g_eactive;
        int nall = g_nall;
        float na = na_of(jt, n);
        float mask = na * (1.f - ae[jt]);
        float ns, nr;
        if (mask > 0.f) {
            int r = jt - ea;
            bool in = (r >= 0 && r < nall);
            ns = in ? (float)g_fi[r] : 0.f;
            nr = in ? (float)g_fj[r] : 0.f;
        } else {
            ns = (float)senders[jt];
            nr = (float)receivers[jt];
        }
        if (!(na > 0.f)) { ns = (float)(N_NODES - 1); nr = (float)(N_NODES - 1); }
        const int ED = N_EDGES * DIM;
        out[ED + jt] = ns;
        out[ED + N_EDGES + jt] = nr;
        out[ED + 2 * N_EDGES + jt] = na;
    }

    int e = q >> 4;
    float4 v = edges4[q];
    float na = na_of(e, n);
    float mask = na * (1.f - ae[e]);
    if (mask > 0.f) {
        const double lo = -0.9999999999999999;  // -(1 - 2^-53)
        uint32_t b0 = (uint32_t)(q * 4);
#pragma unroll
        for (int k = 0; k < 4; ++k) {
            double f = u01d(pbits64(KE0, KE1, b0 + k));
            double u = fmax(lo, f * 2.0 + lo);
            double nrm = 1.4142135623730951 * erfinv64(u);
            float* vp = (k == 0) ? &v.x : (k == 1) ? &v.y : (k == 2) ? &v.z : &v.w;
            *vp = (float)((double)*vp + nrm);
        }
    }
    ((float4*)out)[q] = v;
}

// ============================================================
extern "C" void kernel_launch(void* const* d_in, const int* in_sizes, int n_in,
                              void* d_out, int out_size) {
    const float* nodes     = (const float*)d_in[0];
    const float* edges     = (const float*)d_in[1];
    const int*   receivers = (const int*)d_in[2];
    const int*   senders   = (const int*)d_in[3];
    const float* an        = (const float*)d_in[4];
    const float* ae        = (const float*)d_in[5];
    const float* Wq        = (const float*)d_in[6];
    const float* bq        = (const float*)d_in[7];
    const float* Wp        = (const float*)d_in[8];
    const float* bp        = (const float*)d_in[9];
    float* out = (float*)d_out;

    k_prep<<<256, 256>>>(nodes, Wq, bq, Wp, bp, an);
    k_scancompact<<<1, 1024>>>(ae);
    dim3 ag(64, NCY);
    k_argmax<<<ag, 128>>>(nodes, an);
    k_existfinal<<<1, 256>>>(senders, receivers);
    k_edgetail<<<1024, 256>>>((const float4*)edges, ae, senders, receivers, out);
}

// round 14
// speedup vs baseline: 2.2364x; 2.2364x over previous
#include <cuda_runtime.h>
#include <cstdint>

#define N_NODES 8192
#define DIM 64
#define N_EDGES 16384
#define NEGV -1e10f
#define TINYF 1.17549435e-38f
#define NCY 14       // candidate strides (grid.y) in k_argmax -> 64*14=896 blocks ~= 1 wave
#define QBATCH 12    // candidates batched per block chunk (covers C<=168 in one chunk)

// ============================================================
// threefry2x32 (verified vs Random123 KAT)
// ============================================================
struct U2 { uint32_t a, b; };

__host__ __device__ constexpr uint32_t rotl32(uint32_t v, int r) {
    return (v << r) | (v >> (32 - r));
}

__host__ __device__ constexpr U2 tf2x32(uint32_t k0, uint32_t k1, uint32_t c0, uint32_t c1) {
    uint32_t ks0 = k0, ks1 = k1, ks2 = k0 ^ k1 ^ 0x1BD11BDAu;
    uint32_t x0 = c0 + ks0, x1 = c1 + ks1;
    x0 += x1; x1 = rotl32(x1, 13); x1 ^= x0;
    x0 += x1; x1 = rotl32(x1, 15); x1 ^= x0;
    x0 += x1; x1 = rotl32(x1, 26); x1 ^= x0;
    x0 += x1; x1 = rotl32(x1, 6);  x1 ^= x0;
    x0 += ks1; x1 += ks2 + 1u;
    x0 += x1; x1 = rotl32(x1, 17); x1 ^= x0;
    x0 += x1; x1 = rotl32(x1, 29); x1 ^= x0;
    x0 += x1; x1 = rotl32(x1, 16); x1 ^= x0;
    x0 += x1; x1 = rotl32(x1, 24); x1 ^= x0;
    x0 += ks2; x1 += ks0 + 2u;
    x0 += x1; x1 = rotl32(x1, 13); x1 ^= x0;
    x0 += x1; x1 = rotl32(x1, 15); x1 ^= x0;
    x0 += x1; x1 = rotl32(x1, 26); x1 ^= x0;
    x0 += x1; x1 = rotl32(x1, 6);  x1 ^= x0;
    x0 += ks0; x1 += ks1 + 3u;
    x0 += x1; x1 = rotl32(x1, 17); x1 ^= x0;
    x0 += x1; x1 = rotl32(x1, 29); x1 ^= x0;
    x0 += x1; x1 = rotl32(x1, 16); x1 ^= x0;
    x0 += x1; x1 = rotl32(x1, 24); x1 ^= x0;
    x0 += ks1; x1 += ks2 + 4u;
    x0 += x1; x1 = rotl32(x1, 13); x1 ^= x0;
    x0 += x1; x1 = rotl32(x1, 15); x1 ^= x0;
    x0 += x1; x1 = rotl32(x1, 26); x1 ^= x0;
    x0 += x1; x1 = rotl32(x1, 6);  x1 ^= x0;
    x0 += ks2; x1 += ks0 + 5u;
    return U2{x0, x1};
}

// Partitionable threefry (modern JAX default)
constexpr uint32_t KP0 = tf2x32(0u, 42u, 0u, 0u).a;
constexpr uint32_t KP1 = tf2x32(0u, 42u, 0u, 0u).b;
constexpr uint32_t KE0 = tf2x32(0u, 42u, 0u, 1u).a;
constexpr uint32_t KE1 = tf2x32(0u, 42u, 0u, 1u).b;
constexpr uint32_t KS0 = tf2x32(0u, 42u, 0u, 2u).a;
constexpr uint32_t KS1 = tf2x32(0u, 42u, 0u, 2u).b;

__device__ __forceinline__ uint32_t pbits32(uint32_t k0, uint32_t k1, uint32_t idx) {
    U2 r = tf2x32(k0, k1, 0u, idx);
    return r.a ^ r.b;
}

__device__ __forceinline__ unsigned long long pbits64(uint32_t k0, uint32_t k1, uint32_t idx) {
    U2 r = tf2x32(k0, k1, 0u, idx);
    return ((unsigned long long)r.a << 32) | (unsigned long long)r.b;
}

__device__ __forceinline__ float u01f(uint32_t bits) {
    return __uint_as_float((bits >> 9) | 0x3f800000u) - 1.0f;
}

__device__ __forceinline__ double u01d(unsigned long long bits) {
    return __longlong_as_double((long long)((bits >> 12) | 0x3FF0000000000000ull)) - 1.0;
}

// f64 erfinv: Giles-poly init (~1e-7) + short Newton refinement.
// 1 iter central / 2 tail (quadratic: 1e-7 -> 1e-13), 3 only in w>=16.
__device__ double erfinv64(double u) {
    double au = fabs(u);
    double w = -log1p(-au * au);
    double x;
    const double C = 0.8862269254527580;  // sqrt(pi)/2
    if (w < 5.0) {
        double ww = w - 2.5;
        double p = 2.81022636e-08;
        p = fma(p, ww, 3.43273939e-07);
        p = fma(p, ww, -3.5233877e-06);
        p = fma(p, ww, -4.39150654e-06);
        p = fma(p, ww, 0.00021858087);
        p = fma(p, ww, -0.00125372503);
        p = fma(p, ww, -0.00417768164);
        p = fma(p, ww, 0.246640727);
        p = fma(p, ww, 1.50140941);
        x = p * au;
        x += (au - erf(x)) * C * exp(x * x);          // 1 Newton step
    } else {
        double eps = 1.0 - au;  // exact (au in [0.9966, 1))
        if (w < 16.0) {
            double ww = sqrt(w) - 3.0;
            double p = -0.000200214257;
            p = fma(p, ww, 0.000100950558);
            p = fma(p, ww, 0.00134934322);
            p = fma(p, ww, -0.00367342844);
            p = fma(p, ww, 0.00573950773);
            p = fma(p, ww, -0.0076224613);
            p = fma(p, ww, 0.00943887047);
            p = fma(p, ww, 1.00167406);
            p = fma(p, ww, 2.83297682);
            x = p * au;
            x += (erfc(x) - eps) * C * exp(x * x);    // 2 Newton steps
            x += (erfc(x) - eps) * C * exp(x * x);
        } else {
            double t = -log(eps);
            x = sqrt(t - 0.5 * log(t) - 0.5723649429247001);
            x += (erfc(x) - eps) * C * exp(x * x);    // 3 Newton steps (never hit in practice)
            x += (erfc(x) - eps) * C * exp(x * x);
            x += (erfc(x) - eps) * C * exp(x * x);
        }
    }
    return copysign(x, u);
}

// ============================================================
// Scratch (static device globals)
// ============================================================
__device__ float g_queries[N_NODES * DIM];
__device__ float g_qn[N_NODES];
__device__ float g_hn[N_NODES];
__device__ unsigned char g_gens[N_NODES];
__device__ int g_genlist[N_NODES];
__device__ int g_cand_of[N_NODES];
__device__ unsigned char g_drop[N_NODES];
__device__ int g_gencount;
__device__ unsigned long long g_best[N_NODES];
__device__ float g_cs[N_EDGES];
__device__ int g_eactive;
__device__ int g_fi[N_NODES];
__device__ int g_fj[N_NODES];
__device__ int g_nall;
__device__ int g_nclip;

// ============================================================
// K1: queries/qn/hn/gens. 256 blocks x 256 threads; warp = 4 nodes.
// ============================================================
__global__ void k_prep(const float* __restrict__ nodes, const float* __restrict__ Wq,
                       const float* __restrict__ bq, const float* __restrict__ Wp,
                       const float* __restrict__ bp, const float* __restrict__ an) {
    __shared__ float Wqs[64 * 64];
    __shared__ float bqs[64];
    int tid = threadIdx.x;
    for (int k = tid; k < 4096; k += 256) Wqs[k] = Wq[k];
    if (tid < 64) bqs[tid] = bq[tid];
    __syncthreads();

    int warp = tid >> 5, lane = tid & 31;
    float wp0 = Wp[lane], wp1 = Wp[32 + lane];
    float bp0 = bp[0];

    for (int n = 0; n < 4; ++n) {
        int i = blockIdx.x * 32 + warp * 4 + n;

        float nv0 = nodes[i * 64 + lane];
        float nv1 = nodes[i * 64 + 32 + lane];

        float h = nv0 * nv0 + nv1 * nv1;
        float pdot = nv0 * wp0 + nv1 * wp1;
        for (int o = 16; o; o >>= 1) {
            h += __shfl_xor_sync(0xFFFFFFFFu, h, o);
            pdot += __shfl_xor_sync(0xFFFFFFFFu, pdot, o);
        }

        float acc0 = bqs[lane], acc1 = bqs[32 + lane];
#pragma unroll
        for (int d = 0; d < 32; ++d) {
            float nv = __shfl_sync(0xFFFFFFFFu, nv0, d);
            acc0 = fmaf(nv, Wqs[d * 64 + lane], acc0);
            acc1 = fmaf(nv, Wqs[d * 64 + 32 + lane], acc1);
        }
#pragma unroll
        for (int d = 0; d < 32; ++d) {
            float nv = __shfl_sync(0xFFFFFFFFu, nv1, d);
            acc0 = fmaf(nv, Wqs[(32 + d) * 64 + lane], acc0);
            acc1 = fmaf(nv, Wqs[(32 + d) * 64 + 32 + lane], acc1);
        }
        g_queries[i * 64 + lane] = acc0;
        g_queries[i * 64 + 32 + lane] = acc1;

        float q2 = acc0 * acc0 + acc1 * acc1;
        for (int o = 16; o; o >>= 1) q2 += __shfl_xor_sync(0xFFFFFFFFu, q2, o);

        if (lane == 0) {
            g_hn[i] = h;
            g_qn[i] = q2;
            float x = pdot + bp0;
            float prob = 1.0f / (1.0f + expf(-x));
            double u = u01d(pbits64(KP0, KP1, (uint32_t)i));
            g_gens[i] = (u < (double)(prob * an[i])) ? 1 : 0;
        }
    }
}

// ============================================================
// K2: fused ae-cumsum + gens-compaction via shfl warp scans.
// 1 block x 1024 threads; 4 barriers total.
// ============================================================
__global__ void k_scancompact(const float* __restrict__ ae) {
    __shared__ float wsf[32];
    __shared__ int wsi[32];
    int t = threadIdx.x, w = t >> 5, l = t & 31;

    // ---- Part A: inclusive cumsum of active_edges (16/thread) ----
    float loc[16];
    float s = 0.f;
#pragma unroll
    for (int k = 0; k < 16; ++k) { loc[k] = ae[t * 16 + k]; s += loc[k]; }
    float sc = s;
#pragma unroll
    for (int o = 1; o < 32; o <<= 1) {
        float v = __shfl_up_sync(0xFFFFFFFFu, sc, o);
        if (l >= o) sc += v;
    }
    if (l == 31) wsf[w] = sc;
    __syncthreads();
    if (w == 0) {
        float ws = wsf[l];
#pragma unroll
        for (int o = 1; o < 32; o <<= 1) {
            float v = __shfl_up_sync(0xFFFFFFFFu, ws, o);
            if (l >= o) ws += v;
        }
        wsf[l] = ws;
    }
    __syncthreads();
    float run = (w > 0 ? wsf[w - 1] : 0.f) + (sc - s);
#pragma unroll
    for (int k = 0; k < 16; ++k) { run += loc[k]; g_cs[t * 16 + k] = run; }
    if (t == 1023) g_eactive = (int)wsf[31];

    // ---- Part B: compact gens (8/thread), cand_of, zero best/drop ----
    unsigned char lg[8];
    int si = 0;
#pragma unroll
    for (int k = 0; k < 8; ++k) { lg[k] = g_gens[t * 8 + k]; si += lg[k]; }
    int sci = si;
#pragma unroll
    for (int o = 1; o < 32; o <<= 1) {
        int v = __shfl_up_sync(0xFFFFFFFFu, sci, o);
        if (l >= o) sci += v;
    }
    if (l == 31) wsi[w] = sci;
    __syncthreads();
    if (w == 0) {
        int ws = wsi[l];
#pragma unroll
        for (int o = 1; o < 32; o <<= 1) {
            int v = __shfl_up_sync(0xFFFFFFFFu, ws, o);
            if (l >= o) ws += v;
        }
        wsi[l] = ws;
    }
    __syncthreads();
    int base = (w > 0 ? wsi[w - 1] : 0) + (sci - si);
#pragma unroll
    for (int k = 0; k < 8; ++k) {
        int idx = t * 8 + k;
        if (lg[k]) { g_genlist[base] = idx; g_cand_of[idx] = base; base++; }
        else g_cand_of[idx] = -1;
    }
    if (t == 1023) g_gencount = wsi[31];
    for (int k = t; k < N_NODES; k += 1024) { g_best[k] = 0ull; g_drop[k] = 0; }
}

// ============================================================
// K3: per-candidate argmax_j(score + gumbel_f32)  [R11-proven version]
// grid (64 j-tiles, NCY) x 128. QBATCH candidates per chunk.
// warp shfl max -> smem atomic -> 1 global atomic per candidate.
// ============================================================
__global__ void k_argmax(const float* __restrict__ nodes, const float* __restrict__ an) {
    __shared__ float tile[128 * 65];
    __shared__ float qs[QBATCH * 64];
    __shared__ float qn_s[QBATCH];
    __shared__ int ii_s[QBATCH];
    __shared__ unsigned long long sbest[QBATCH];
    int t = threadIdx.x;
    int j0 = blockIdx.x * 128;
    for (int k = t; k < 128 * 64; k += 128)
        tile[(k >> 6) * 65 + (k & 63)] = nodes[j0 * 64 + k];
    int j = j0 + t;
    float hnj = g_hn[j];
    float anj = an[j];
    __syncthreads();

    int C = g_gencount;
    for (int cbase = blockIdx.y; cbase < C; cbase += NCY * QBATCH) {
        for (int load = t; load < QBATCH * 64; load += 128) {
            int k = load >> 6, d = load & 63;
            int c = cbase + k * NCY;
            if (c < C) {
                int i = g_genlist[c];
                qs[k * 64 + d] = g_queries[i * 64 + d];
                if (d == 0) { qn_s[k] = g_qn[i]; ii_s[k] = i; }
            }
        }
        if (t < QBATCH) sbest[t] = 0ull;
        __syncthreads();
#pragma unroll 1
        for (int k = 0; k < QBATCH; ++k) {
            int c = cbase + k * NCY;
            if (c >= C) break;
            int i = ii_s[k];
            float num = 0.f;
#pragma unroll
            for (int d = 0; d < 64; ++d) num = fmaf(qs[k * 64 + d], tile[t * 65 + d], num);
            float s = num / (sqrtf(qn_s[k] * hnj) + 1e-8f);
            s = fminf(fmaxf(s, -10000.f), 10000.f);
            if (!(anj > 0.f)) s = NEGV;
            if (j == i) s = NEGV;
            uint32_t idx = (uint32_t)i * (uint32_t)N_NODES + (uint32_t)j;
            float f = u01f(pbits32(KS0, KS1, idx));
            float u = fmaxf(TINYF, f + TINYF);
            float g = -logf(-logf(u));
            float v = s + g;
            uint32_t ord = __float_as_uint(v);
            ord = (ord & 0x80000000u) ? ~ord : (ord | 0x80000000u);
            unsigned long long enc =
                ((unsigned long long)ord << 32) | (unsigned long long)(~(uint32_t)j);
#pragma unroll
            for (int o = 16; o; o >>= 1) {
                unsigned long long other = __shfl_xor_sync(0xFFFFFFFFu, enc, o);
                if (other > enc) enc = other;
            }
            if ((t & 31) == 0) atomicMax(&sbest[k], enc);
        }
        __syncthreads();
        if (t < QBATCH) {
            int c = cbase + t * NCY;
            if (c < C && sbest[t]) atomicMax(&g_best[c], sbest[t]);
        }
        __syncthreads();
    }
}

// ============================================================
// K4: edge-exists check — wide grid (latency in parallel)
// ============================================================
__global__ void k_exist2(const int* __restrict__ senders, const int* __restrict__ receivers) {
    int e = blockIdx.x * blockDim.x + threadIdx.x;
    if (e >= N_EDGES) return;
    int i = senders[e];
    int c = g_cand_of[i];
    if (c >= 0) {
        int sel = (int)(~(uint32_t)(g_best[c] & 0xFFFFFFFFull));
        if (receivers[e] == sel) g_drop[c] = 1;
    }
}

// ============================================================
// K5: parallel ordered compaction after drops + clip (1 block x 256)
// ============================================================
__global__ void k_final2() {
    __shared__ int warpcnt[8];
    __shared__ int warpoff[8];
    __shared__ int running;
    int t = threadIdx.x;
    if (t == 0) running = 0;
    __syncthreads();
    int C = g_gencount;
    for (int cbase = 0; cbase < C; cbase += 256) {
        int c = cbase + t;
        bool keep = (c < C) && !g_drop[c];
        unsigned mask = __ballot_sync(0xFFFFFFFFu, keep);
        int w = t >> 5, l = t & 31;
        if (l == 0) warpcnt[w] = __popc(mask);
        __syncthreads();
        if (t == 0) {
            int s = running;
#pragma unroll
            for (int k = 0; k < 8; ++k) { warpoff[k] = s; s += warpcnt[k]; }
            running = s;
        }
        __syncthreads();
        if (keep) {
            int pos = warpoff[w] + __popc(mask & ((1u << l) - 1u));
            g_fi[pos] = g_genlist[c];
            g_fj[pos] = (int)(~(uint32_t)(g_best[c] & 0xFFFFFFFFull));
        }
        __syncthreads();
    }
    if (t == 0) {
        int n = running;
        int ea = g_eactive;
        int allowed = N_EDGES - ea - 1;
        if (allowed < 0) allowed = 0;
        g_nall = n;
        g_nclip = (n < allowed) ? n : allowed;
    }
}

// windowed-any from cumsum: naedges[j]
__device__ __forceinline__ float na_of(int j, int n) {
    float c = g_cs[j];
    int pidx = j - n - 1;
    float prev = (pidx >= 0) ? g_cs[pidx] : 0.f;
    float na = ((c - prev) > 0.f) ? 1.f : 0.f;
    if (j == N_EDGES - 1) na = 0.f;
    return na;
}

// ============================================================
// K6: fused tail (nsend/nrec/naedges) + new_edges (f64 noise)
// scalar layout: one element per thread (max erfinv parallelism)
// ============================================================
__global__ void k_edgetail(const float* __restrict__ edges, const float* __restrict__ ae,
                           const int* __restrict__ senders, const int* __restrict__ receivers,
                           float* __restrict__ out) {
    int idx = blockIdx.x * blockDim.x + threadIdx.x;
    if (idx >= N_EDGES * DIM) return;
    int n = g_nclip;

    if (idx < N_EDGES) {
        int jt = idx;
        int ea = g_eactive;
        int nall = g_nall;
        float na = na_of(jt, n);
        float mask = na * (1.f - ae[jt]);
        float ns, nr;
        if (mask > 0.f) {
            int r = jt - ea;
            bool in = (r >= 0 && r < nall);
            ns = in ? (float)g_fi[r] : 0.f;
            nr = in ? (float)g_fj[r] : 0.f;
        } else {
            ns = (float)senders[jt];
            nr = (float)receivers[jt];
        }
        if (!(na > 0.f)) { ns = (float)(N_NODES - 1); nr = (float)(N_NODES - 1); }
        const int ED = N_EDGES * DIM;
        out[ED + jt] = ns;
        out[ED + N_EDGES + jt] = nr;
        out[ED + 2 * N_EDGES + jt] = na;
    }

    int e = idx >> 6;
    float v = edges[idx];
    float na = na_of(e, n);
    float mask = na * (1.f - ae[e]);
    if (mask > 0.f) {
        double f = u01d(pbits64(KE0, KE1, (uint32_t)idx));
        const double lo = -0.9999999999999999;  // -(1 - 2^-53)
        double u = fmax(lo, f * 2.0 + lo);
        double nrm = 1.4142135623730951 * erfinv64(u);
        v = (float)((double)v + nrm);
    }
    out[idx] = v;
}

// ============================================================
extern "C" void kernel_launch(void* const* d_in, const int* in_sizes, int n_in,
                              void* d_out, int out_size) {
    const float* nodes     = (const float*)d_in[0];
    const float* edges     = (const float*)d_in[1];
    const int*   receivers = (const int*)d_in[2];
    const int*   senders   = (const int*)d_in[3];
    const float* an        = (const float*)d_in[4];
    const float* ae        = (const float*)d_in[5];
    const float* Wq        = (const float*)d_in[6];
    const float* bq        = (const float*)d_in[7];
    const float* Wp        = (const float*)d_in[8];
    const float* bp        = (const float*)d_in[9];
    float* out = (float*)d_out;

    k_prep<<<256, 256>>>(nodes, Wq, bq, Wp, bp, an);
    k_scancompact<<<1, 1024>>>(ae);
    dim3 ag(64, NCY);
    k_argmax<<<ag, 128>>>(nodes, an);
    k_exist2<<<64, 256>>>(senders, receivers);
    k_final2<<<1, 256>>>();
    k_edgetail<<<4096, 256>>>(edges, ae, senders, receivers, out);
}

// round 15
// speedup vs baseline: 2.3044x; 1.0304x over previous
#include <cuda_runtime.h>
#include <cstdint>

#define N_NODES 8192
#define DIM 64
#define N_EDGES 16384
#define NEGV -1e10f
#define TINYF 1.17549435e-38f
#define NCY 9        // candidate strides (grid.y) in k_argmax -> 64*9=576 blocks ~= 1 wave @4/SM
#define QBATCH 20    // candidates per chunk (NCY*QBATCH=180 covers C in one chunk)

// ============================================================
// threefry2x32 (verified vs Random123 KAT)
// ============================================================
struct U2 { uint32_t a, b; };

__host__ __device__ constexpr uint32_t rotl32(uint32_t v, int r) {
    return (v << r) | (v >> (32 - r));
}

__host__ __device__ constexpr U2 tf2x32(uint32_t k0, uint32_t k1, uint32_t c0, uint32_t c1) {
    uint32_t ks0 = k0, ks1 = k1, ks2 = k0 ^ k1 ^ 0x1BD11BDAu;
    uint32_t x0 = c0 + ks0, x1 = c1 + ks1;
    x0 += x1; x1 = rotl32(x1, 13); x1 ^= x0;
    x0 += x1; x1 = rotl32(x1, 15); x1 ^= x0;
    x0 += x1; x1 = rotl32(x1, 26); x1 ^= x0;
    x0 += x1; x1 = rotl32(x1, 6);  x1 ^= x0;
    x0 += ks1; x1 += ks2 + 1u;
    x0 += x1; x1 = rotl32(x1, 17); x1 ^= x0;
    x0 += x1; x1 = rotl32(x1, 29); x1 ^= x0;
    x0 += x1; x1 = rotl32(x1, 16); x1 ^= x0;
    x0 += x1; x1 = rotl32(x1, 24); x1 ^= x0;
    x0 += ks2; x1 += ks0 + 2u;
    x0 += x1; x1 = rotl32(x1, 13); x1 ^= x0;
    x0 += x1; x1 = rotl32(x1, 15); x1 ^= x0;
    x0 += x1; x1 = rotl32(x1, 26); x1 ^= x0;
    x0 += x1; x1 = rotl32(x1, 6);  x1 ^= x0;
    x0 += ks0; x1 += ks1 + 3u;
    x0 += x1; x1 = rotl32(x1, 17); x1 ^= x0;
    x0 += x1; x1 = rotl32(x1, 29); x1 ^= x0;
    x0 += x1; x1 = rotl32(x1, 16); x1 ^= x0;
    x0 += x1; x1 = rotl32(x1, 24); x1 ^= x0;
    x0 += ks1; x1 += ks2 + 4u;
    x0 += x1; x1 = rotl32(x1, 13); x1 ^= x0;
    x0 += x1; x1 = rotl32(x1, 15); x1 ^= x0;
    x0 += x1; x1 = rotl32(x1, 26); x1 ^= x0;
    x0 += x1; x1 = rotl32(x1, 6);  x1 ^= x0;
    x0 += ks2; x1 += ks0 + 5u;
    return U2{x0, x1};
}

// Partitionable threefry (modern JAX default)
constexpr uint32_t KP0 = tf2x32(0u, 42u, 0u, 0u).a;
constexpr uint32_t KP1 = tf2x32(0u, 42u, 0u, 0u).b;
constexpr uint32_t KE0 = tf2x32(0u, 42u, 0u, 1u).a;
constexpr uint32_t KE1 = tf2x32(0u, 42u, 0u, 1u).b;
constexpr uint32_t KS0 = tf2x32(0u, 42u, 0u, 2u).a;
constexpr uint32_t KS1 = tf2x32(0u, 42u, 0u, 2u).b;

__device__ __forceinline__ uint32_t pbits32(uint32_t k0, uint32_t k1, uint32_t idx) {
    U2 r = tf2x32(k0, k1, 0u, idx);
    return r.a ^ r.b;
}

__device__ __forceinline__ unsigned long long pbits64(uint32_t k0, uint32_t k1, uint32_t idx) {
    U2 r = tf2x32(k0, k1, 0u, idx);
    return ((unsigned long long)r.a << 32) | (unsigned long long)r.b;
}

__device__ __forceinline__ float u01f(uint32_t bits) {
    return __uint_as_float((bits >> 9) | 0x3f800000u) - 1.0f;
}

__device__ __forceinline__ double u01d(unsigned long long bits) {
    return __longlong_as_double((long long)((bits >> 12) | 0x3FF0000000000000ull)) - 1.0;
}

// f64 erfinv: Giles-poly init (~1e-7) + short Newton refinement.
__device__ double erfinv64(double u) {
    double au = fabs(u);
    double w = -log1p(-au * au);
    double x;
    const double C = 0.8862269254527580;  // sqrt(pi)/2
    if (w < 5.0) {
        double ww = w - 2.5;
        double p = 2.81022636e-08;
        p = fma(p, ww, 3.43273939e-07);
        p = fma(p, ww, -3.5233877e-06);
        p = fma(p, ww, -4.39150654e-06);
        p = fma(p, ww, 0.00021858087);
        p = fma(p, ww, -0.00125372503);
        p = fma(p, ww, -0.00417768164);
        p = fma(p, ww, 0.246640727);
        p = fma(p, ww, 1.50140941);
        x = p * au;
        x += (au - erf(x)) * C * exp(x * x);          // 1 Newton step
    } else {
        double eps = 1.0 - au;  // exact (au in [0.9966, 1))
        if (w < 16.0) {
            double ww = sqrt(w) - 3.0;
            double p = -0.000200214257;
            p = fma(p, ww, 0.000100950558);
            p = fma(p, ww, 0.00134934322);
            p = fma(p, ww, -0.00367342844);
            p = fma(p, ww, 0.00573950773);
            p = fma(p, ww, -0.0076224613);
            p = fma(p, ww, 0.00943887047);
            p = fma(p, ww, 1.00167406);
            p = fma(p, ww, 2.83297682);
            x = p * au;
            x += (erfc(x) - eps) * C * exp(x * x);    // 2 Newton steps
            x += (erfc(x) - eps) * C * exp(x * x);
        } else {
            double t = -log(eps);
            x = sqrt(t - 0.5 * log(t) - 0.5723649429247001);
            x += (erfc(x) - eps) * C * exp(x * x);    // 3 Newton steps (never hit in practice)
            x += (erfc(x) - eps) * C * exp(x * x);
            x += (erfc(x) - eps) * C * exp(x * x);
        }
    }
    return copysign(x, u);
}

// ============================================================
// Scratch (static device globals)
// ============================================================
__device__ float g_queries[N_NODES * DIM];
__device__ float g_qn[N_NODES];
__device__ float g_hn[N_NODES];
__device__ unsigned char g_gens[N_NODES];
__device__ int g_genlist[N_NODES];
__device__ int g_cand_of[N_NODES];
__device__ unsigned char g_drop[N_NODES];
__device__ int g_gencount;
__device__ unsigned long long g_best[N_NODES];
__device__ float g_cs[N_EDGES];
__device__ int g_eactive;
__device__ int g_fi[N_NODES];
__device__ int g_fj[N_NODES];
__device__ int g_nall;
__device__ int g_nclip;

// ============================================================
// K1: queries/qn/hn/gens. 256 blocks x 256 threads; warp = 4 nodes.
// ============================================================
__global__ void k_prep(const float* __restrict__ nodes, const float* __restrict__ Wq,
                       const float* __restrict__ bq, const float* __restrict__ Wp,
                       const float* __restrict__ bp, const float* __restrict__ an) {
    __shared__ float Wqs[64 * 64];
    __shared__ float bqs[64];
    int tid = threadIdx.x;
    for (int k = tid; k < 4096; k += 256) Wqs[k] = Wq[k];
    if (tid < 64) bqs[tid] = bq[tid];
    __syncthreads();

    int warp = tid >> 5, lane = tid & 31;
    float wp0 = Wp[lane], wp1 = Wp[32 + lane];
    float bp0 = bp[0];

    for (int n = 0; n < 4; ++n) {
        int i = blockIdx.x * 32 + warp * 4 + n;

        float nv0 = nodes[i * 64 + lane];
        float nv1 = nodes[i * 64 + 32 + lane];

        float h = nv0 * nv0 + nv1 * nv1;
        float pdot = nv0 * wp0 + nv1 * wp1;
        for (int o = 16; o; o >>= 1) {
            h += __shfl_xor_sync(0xFFFFFFFFu, h, o);
            pdot += __shfl_xor_sync(0xFFFFFFFFu, pdot, o);
        }

        float acc0 = bqs[lane], acc1 = bqs[32 + lane];
#pragma unroll
        for (int d = 0; d < 32; ++d) {
            float nv = __shfl_sync(0xFFFFFFFFu, nv0, d);
            acc0 = fmaf(nv, Wqs[d * 64 + lane], acc0);
            acc1 = fmaf(nv, Wqs[d * 64 + 32 + lane], acc1);
        }
#pragma unroll
        for (int d = 0; d < 32; ++d) {
            float nv = __shfl_sync(0xFFFFFFFFu, nv1, d);
            acc0 = fmaf(nv, Wqs[(32 + d) * 64 + lane], acc0);
            acc1 = fmaf(nv, Wqs[(32 + d) * 64 + 32 + lane], acc1);
        }
        g_queries[i * 64 + lane] = acc0;
        g_queries[i * 64 + 32 + lane] = acc1;

        float q2 = acc0 * acc0 + acc1 * acc1;
        for (int o = 16; o; o >>= 1) q2 += __shfl_xor_sync(0xFFFFFFFFu, q2, o);

        if (lane == 0) {
            g_hn[i] = h;
            g_qn[i] = q2;
            float x = pdot + bp0;
            float prob = 1.0f / (1.0f + expf(-x));
            double u = u01d(pbits64(KP0, KP1, (uint32_t)i));
            g_gens[i] = (u < (double)(prob * an[i])) ? 1 : 0;
        }
    }
}

// ============================================================
// K2: fused ae-cumsum + gens-compaction via shfl warp scans.
// ============================================================
__global__ void k_scancompact(const float* __restrict__ ae) {
    __shared__ float wsf[32];
    __shared__ int wsi[32];
    int t = threadIdx.x, w = t >> 5, l = t & 31;

    float loc[16];
    float s = 0.f;
#pragma unroll
    for (int k = 0; k < 16; ++k) { loc[k] = ae[t * 16 + k]; s += loc[k]; }
    float sc = s;
#pragma unroll
    for (int o = 1; o < 32; o <<= 1) {
        float v = __shfl_up_sync(0xFFFFFFFFu, sc, o);
        if (l >= o) sc += v;
    }
    if (l == 31) wsf[w] = sc;
    __syncthreads();
    if (w == 0) {
        float ws = wsf[l];
#pragma unroll
        for (int o = 1; o < 32; o <<= 1) {
            float v = __shfl_up_sync(0xFFFFFFFFu, ws, o);
            if (l >= o) ws += v;
        }
        wsf[l] = ws;
    }
    __syncthreads();
    float run = (w > 0 ? wsf[w - 1] : 0.f) + (sc - s);
#pragma unroll
    for (int k = 0; k < 16; ++k) { run += loc[k]; g_cs[t * 16 + k] = run; }
    if (t == 1023) g_eactive = (int)wsf[31];

    unsigned char lg[8];
    int si = 0;
#pragma unroll
    for (int k = 0; k < 8; ++k) { lg[k] = g_gens[t * 8 + k]; si += lg[k]; }
    int sci = si;
#pragma unroll
    for (int o = 1; o < 32; o <<= 1) {
        int v = __shfl_up_sync(0xFFFFFFFFu, sci, o);
        if (l >= o) sci += v;
    }
    if (l == 31) wsi[w] = sci;
    __syncthreads();
    if (w == 0) {
        int ws = wsi[l];
#pragma unroll
        for (int o = 1; o < 32; o <<= 1) {
            int v = __shfl_up_sync(0xFFFFFFFFu, ws, o);
            if (l >= o) ws += v;
        }
        wsi[l] = ws;
    }
    __syncthreads();
    int base = (w > 0 ? wsi[w - 1] : 0) + (sci - si);
#pragma unroll
    for (int k = 0; k < 8; ++k) {
        int idx = t * 8 + k;
        if (lg[k]) { g_genlist[base] = idx; g_cand_of[idx] = base; base++; }
        else g_cand_of[idx] = -1;
    }
    if (t == 1023) g_gencount = wsi[31];
    for (int k = t; k < N_NODES; k += 1024) { g_best[k] = 0ull; g_drop[k] = 0; }
}

// ============================================================
// K3: per-candidate argmax_j(score + gumbel_f32)
// Node row held in 16 float4 REGISTERS (1 gmem load each, L2-hot);
// qs read as float4 smem BROADCAST -> smem cycles/warp-iter 80 -> 16.
// FMA order strictly sequential (bit-identical scores).
// ============================================================
__global__ void k_argmax(const float* __restrict__ nodes, const float* __restrict__ an) {
    __shared__ float4 qs4[QBATCH * 16];
    __shared__ float qn_s[QBATCH];
    __shared__ int ii_s[QBATCH];
    __shared__ unsigned long long sbest[QBATCH];
    int t = threadIdx.x;
    int j = blockIdx.x * 128 + t;

    float4 row[16];
    const float4* nr = (const float4*)(nodes + (size_t)j * 64);
#pragma unroll
    for (int d4 = 0; d4 < 16; ++d4) row[d4] = nr[d4];
    float hnj = g_hn[j];
    float anj = an[j];

    int C = g_gencount;
    for (int cbase = blockIdx.y; cbase < C; cbase += NCY * QBATCH) {
        for (int q = t; q < QBATCH * 16; q += 128) {
            int k = q >> 4, d4 = q & 15;
            int c = cbase + k * NCY;
            if (c < C) {
                int i = g_genlist[c];
                qs4[q] = ((const float4*)(g_queries + (size_t)i * 64))[d4];
                if (d4 == 0) { qn_s[k] = g_qn[i]; ii_s[k] = i; }
            }
        }
        if (t < QBATCH) sbest[t] = 0ull;
        __syncthreads();
#pragma unroll 1
        for (int k = 0; k < QBATCH; ++k) {
            int c = cbase + k * NCY;
            if (c >= C) break;
            int i = ii_s[k];
            float num = 0.f;
#pragma unroll
            for (int d4 = 0; d4 < 16; ++d4) {
                float4 q = qs4[k * 16 + d4];   // conflict-free warp broadcast
                num = fmaf(q.x, row[d4].x, num);
                num = fmaf(q.y, row[d4].y, num);
                num = fmaf(q.z, row[d4].z, num);
                num = fmaf(q.w, row[d4].w, num);
            }
            float s = num / (sqrtf(qn_s[k] * hnj) + 1e-8f);
            s = fminf(fmaxf(s, -10000.f), 10000.f);
            if (!(anj > 0.f)) s = NEGV;
            if (j == i) s = NEGV;
            uint32_t idx = (uint32_t)i * (uint32_t)N_NODES + (uint32_t)j;
            float f = u01f(pbits32(KS0, KS1, idx));
            float u = fmaxf(TINYF, f + TINYF);
            float g = -logf(-logf(u));
            float v = s + g;
            uint32_t ord = __float_as_uint(v);
            ord = (ord & 0x80000000u) ? ~ord : (ord | 0x80000000u);
            unsigned long long enc =
                ((unsigned long long)ord << 32) | (unsigned long long)(~(uint32_t)j);
#pragma unroll
            for (int o = 16; o; o >>= 1) {
                unsigned long long other = __shfl_xor_sync(0xFFFFFFFFu, enc, o);
                if (other > enc) enc = other;
            }
            if ((t & 31) == 0) atomicMax(&sbest[k], enc);
        }
        __syncthreads();
        if (t < QBATCH) {
            int c = cbase + t * NCY;
            if (c < C && sbest[t]) atomicMax(&g_best[c], sbest[t]);
        }
        __syncthreads();
    }
}

// ============================================================
// K4: edge-exists check — wide grid (latency in parallel)
// ============================================================
__global__ void k_exist2(const int* __restrict__ senders, const int* __restrict__ receivers) {
    int e = blockIdx.x * blockDim.x + threadIdx.x;
    if (e >= N_EDGES) return;
    int i = senders[e];
    int c = g_cand_of[i];
    if (c >= 0) {
        int sel = (int)(~(uint32_t)(g_best[c] & 0xFFFFFFFFull));
        if (receivers[e] == sel) g_drop[c] = 1;
    }
}

// ============================================================
// K5: parallel ordered compaction after drops + clip (1 block x 256)
// ============================================================
__global__ void k_final2() {
    __shared__ int warpcnt[8];
    __shared__ int warpoff[8];
    __shared__ int running;
    int t = threadIdx.x;
    if (t == 0) running = 0;
    __syncthreads();
    int C = g_gencount;
    for (int cbase = 0; cbase < C; cbase += 256) {
        int c = cbase + t;
        bool keep = (c < C) && !g_drop[c];
        unsigned mask = __ballot_sync(0xFFFFFFFFu, keep);
        int w = t >> 5, l = t & 31;
        if (l == 0) warpcnt[w] = __popc(mask);
        __syncthreads();
        if (t == 0) {
            int s = running;
#pragma unroll
            for (int k = 0; k < 8; ++k) { warpoff[k] = s; s += warpcnt[k]; }
            running = s;
        }
        __syncthreads();
        if (keep) {
            int pos = warpoff[w] + __popc(mask & ((1u << l) - 1u));
            g_fi[pos] = g_genlist[c];
            g_fj[pos] = (int)(~(uint32_t)(g_best[c] & 0xFFFFFFFFull));
        }
        __syncthreads();
    }
    if (t == 0) {
        int n = running;
        int ea = g_eactive;
        int allowed = N_EDGES - ea - 1;
        if (allowed < 0) allowed = 0;
        g_nall = n;
        g_nclip = (n < allowed) ? n : allowed;
    }
}

// windowed-any from cumsum: naedges[j]
__device__ __forceinline__ float na_of(int j, int n) {
    float c = g_cs[j];
    int pidx = j - n - 1;
    float prev = (pidx >= 0) ? g_cs[pidx] : 0.f;
    float na = ((c - prev) > 0.f) ? 1.f : 0.f;
    if (j == N_EDGES - 1) na = 0.f;
    return na;
}

// ============================================================
// K6: fused tail (nsend/nrec/naedges) + new_edges (f64 noise)
// ============================================================
__global__ void k_edgetail(const float* __restrict__ edges, const float* __restrict__ ae,
                           const int* __restrict__ senders, const int* __restrict__ receivers,
                           float* __restrict__ out) {
    int idx = blockIdx.x * blockDim.x + threadIdx.x;
    if (idx >= N_EDGES * DIM) return;
    int n = g_nclip;

    if (idx < N_EDGES) {
        int jt = idx;
        int ea = g_eactive;
        int nall = g_nall;
        float na = na_of(jt, n);
        float mask = na * (1.f - ae[jt]);
        float ns, nr;
        if (mask > 0.f) {
            int r = jt - ea;
            bool in = (r >= 0 && r < nall);
            ns = in ? (float)g_fi[r] : 0.f;
            nr = in ? (float)g_fj[r] : 0.f;
        } else {
            ns = (float)senders[jt];
            nr = (float)receivers[jt];
        }
        if (!(na > 0.f)) { ns = (float)(N_NODES - 1); nr = (float)(N_NODES - 1); }
        const int ED = N_EDGES * DIM;
        out[ED + jt] = ns;
        out[ED + N_EDGES + jt] = nr;
        out[ED + 2 * N_EDGES + jt] = na;
    }

    int e = idx >> 6;
    float v = edges[idx];
    float na = na_of(e, n);
    float mask = na * (1.f - ae[e]);
    if (mask > 0.f) {
        double f = u01d(pbits64(KE0, KE1, (uint32_t)idx));
        const double lo = -0.9999999999999999;  // -(1 - 2^-53)
        double u = fmax(lo, f * 2.0 + lo);
        double nrm = 1.4142135623730951 * erfinv64(u);
        v = (float)((double)v + nrm);
    }
    out[idx] = v;
}

// ============================================================
extern "C" void kernel_launch(void* const* d_in, const int* in_sizes, int n_in,
                              void* d_out, int out_size) {
    const float* nodes     = (const float*)d_in[0];
    const float* edges     = (const float*)d_in[1];
    const int*   receivers = (const int*)d_in[2];
    const int*   senders   = (const int*)d_in[3];
    const float* an        = (const float*)d_in[4];
    const float* ae        = (const float*)d_in[5];
    const float* Wq        = (const float*)d_in[6];
    const float* bq        = (const float*)d_in[7];
    const float* Wp        = (const float*)d_in[8];
    const float* bp        = (const float*)d_in[9];
    float* out = (float*)d_out;

    k_prep<<<256, 256>>>(nodes, Wq, bq, Wp, bp, an);
    k_scancompact<<<1, 1024>>>(ae);
    dim3 ag(64, NCY);
    k_argmax<<<ag, 128>>>(nodes, an);
    k_exist2<<<64, 256>>>(senders, receivers);
    k_final2<<<1, 256>>>();
    k_edgetail<<<4096, 256>>>(edges, ae, senders, receivers, out);
}